// round 1
// baseline (speedup 1.0000x reference)
#include <cuda_runtime.h>

// Problem constants
#define NB 16
#define NS 128
#define NC 64
#define NH 8
#define NHD 64
#define ND 512
#define NM 256   // D/2

// ---------------- scratch (device globals; no allocation allowed) ----------
__device__ float g_sA[NH];        // scale * (Wq_h . Wk_h)
__device__ float g_sC[NH];        // scale * (bq_h . Wk_h)
__device__ float g_P[NH * NM];    // P[h][m] = sum_dd Wv[h*64+dd] * Ws[(h*64+dd), m]
__device__ float g_p0[NM];        // bv @ Ws + bs
__device__ float g_Q[NH * ND];    // Q[h][d] = sum_m P[h][m] * We[m, d]
__device__ float g_q0[ND];        // p0 @ We + be
__device__ float g_R[ND];         // Wv * Wf (elementwise)
__device__ float g_r0[ND];        // bv * Wf

__device__ __forceinline__ float warp_sum(float v) {
#pragma unroll
    for (int o = 16; o; o >>= 1) v += __shfl_xor_sync(0xffffffffu, v, o);
    return v;
}

// ---------------- precompute 1: per-head score scalars + SE folding stage 1
__global__ void __launch_bounds__(512) k_pre1(
    const float* __restrict__ Wq, const float* __restrict__ bq,
    const float* __restrict__ Wk,
    const float* __restrict__ Wv, const float* __restrict__ bv,
    const float* __restrict__ Ws, const float* __restrict__ bs,
    const float* __restrict__ Wf)
{
    int tid = threadIdx.x;            // 512 threads, one per d
    __shared__ float wA[16], wC[16];

    float a = Wq[tid] * Wk[tid];
    float c = bq[tid] * Wk[tid];
    a = warp_sum(a);
    c = warp_sum(c);
    int w = tid >> 5;
    if ((tid & 31) == 0) { wA[w] = a; wC[w] = c; }

    g_R[tid]  = Wv[tid] * Wf[tid];
    g_r0[tid] = bv[tid] * Wf[tid];

    __syncthreads();
    if (tid < NH) {
        // head h = two warps (2h, 2h+1); scale = 1/sqrt(64) = 0.125
        g_sA[tid] = (wA[2 * tid] + wA[2 * tid + 1]) * 0.125f;
        g_sC[tid] = (wC[2 * tid] + wC[2 * tid + 1]) * 0.125f;
    }

    if (tid < NM) {
        float acc = bs[tid];
#pragma unroll 8
        for (int j = 0; j < ND; j++)
            acc = fmaf(bv[j], Ws[j * NM + tid], acc);
        g_p0[tid] = acc;
    }

    for (int idx = tid; idx < NH * NM; idx += 512) {
        int h = idx >> 8;          // /256
        int m = idx & (NM - 1);
        float acc = 0.f;
#pragma unroll
        for (int dd = 0; dd < NHD; dd++) {
            int j = h * NHD + dd;
            acc = fmaf(Wv[j], Ws[j * NM + m], acc);
        }
        g_P[idx] = acc;
    }
}

// ---------------- precompute 2: fold SE MLP second layer --------------------
__global__ void __launch_bounds__(512) k_pre2(
    const float* __restrict__ We, const float* __restrict__ be)
{
    int d = threadIdx.x;          // 512
    int hb = blockIdx.x;          // 0..8
    if (hb < NH) {
        float acc = 0.f;
#pragma unroll 8
        for (int m = 0; m < NM; m++)
            acc = fmaf(g_P[hb * NM + m], We[m * ND + d], acc);
        g_Q[hb * ND + d] = acc;
    } else {
        float acc = be[d];
#pragma unroll 8
        for (int m = 0; m < NM; m++)
            acc = fmaf(g_p0[m], We[m * ND + d], acc);
        g_q0[d] = acc;
    }
}

// ---------------- main: per-(b,c) softmax means + SE + output ---------------
__global__ void __launch_bounds__(256) k_main(
    const float* __restrict__ x,
    const float* __restrict__ bf,
    float* __restrict__ out)
{
    __shared__ float xs[NS];
    __shared__ float xv[NH][NS];
    __shared__ float exc[ND];
    __shared__ float sA[NH], sC[NH], sqv[NH], w1[NH];
    __shared__ float red[8];
    __shared__ float smax, smin, w0t;

    int tid = threadIdx.x;
    int c = blockIdx.x;
    int b = blockIdx.y;
    const float* xp = x + (size_t)(b * NS) * NC + c;

    if (tid < NS) xs[tid] = xp[tid * NC];
    if (tid < NH) { sA[tid] = g_sA[tid]; sC[tid] = g_sC[tid]; }
    __syncthreads();

    // min/max of xs (softmax stability), warp 0
    if (tid < 32) {
        float mx = -1e30f, mn = 1e30f;
#pragma unroll
        for (int k = tid; k < NS; k += 32) {
            float v = xs[k];
            mx = fmaxf(mx, v);
            mn = fminf(mn, v);
        }
#pragma unroll
        for (int o = 16; o; o >>= 1) {
            mx = fmaxf(mx, __shfl_xor_sync(0xffffffffu, mx, o));
            mn = fminf(mn, __shfl_xor_sync(0xffffffffu, mn, o));
        }
        if (tid == 0) { smax = mx; smin = mn; }
    }
    __syncthreads();

    float mxv = smax, mnv = smin;

    // 1024 (h,q) tasks; each: softmax-weighted mean of xs under weights exp(beta*x_k)
    for (int p = tid; p < NH * NS; p += 256) {
        int h = p >> 7;
        int q = p & (NS - 1);
        float beta = fmaf(sA[h], xs[q], sC[h]);
        float bm = (beta >= 0.f) ? mxv : mnv;      // max of beta*x_k
        float shift = -beta * bm;
        float den = 0.f, num = 0.f;
#pragma unroll 4
        for (int k = 0; k < NS; k++) {
            float xk = xs[k];
            float e = __expf(fmaf(beta, xk, shift));
            den += e;
            num = fmaf(xk, e, num);
        }
        xv[h][q] = num / den;
    }
    __syncthreads();

    // per-head mean over q (squeeze): warp w handles head w
    int w = tid >> 5, lane = tid & 31;
    {
        float s = xv[w][lane] + xv[w][lane + 32] + xv[w][lane + 64] + xv[w][lane + 96];
        s = warp_sum(s);
        if (lane == 0) sqv[w] = s * (1.0f / NS);
    }
    __syncthreads();

    // excitation: exc[d] = sigmoid(sum_h sqv[h]*Q[h][d] + q0[d])
    for (int d = tid; d < ND; d += 256) {
        float u = g_q0[d];
#pragma unroll
        for (int h = 0; h < NH; h++)
            u = fmaf(sqv[h], g_Q[h * ND + d], u);
        exc[d] = __fdividef(1.0f, 1.0f + __expf(-u));
    }
    __syncthreads();

    // fold output projection: w1[h] = sum_dd R[h*64+dd]*exc[...]
    {
        int d0 = w * NHD + lane;
        float s = g_R[d0] * exc[d0] + g_R[d0 + 32] * exc[d0 + 32];
        s = warp_sum(s);
        if (lane == 0) w1[w] = s;
    }
    // w0 = sum_d r0[d]*exc[d]
    {
        float pv = g_r0[tid] * exc[tid] + g_r0[tid + 256] * exc[tid + 256];
        pv = warp_sum(pv);
        if (lane == 0) red[w] = pv;
    }
    __syncthreads();
    if (tid == 0) {
        float s = 0.f;
#pragma unroll
        for (int i = 0; i < 8; i++) s += red[i];
        w0t = s + bf[0];
    }
    __syncthreads();

    // final: out[b,s,c] = sum_h xv[h][s]*w1[h] + w0
    if (tid < NS) {
        float o = w0t;
#pragma unroll
        for (int h = 0; h < NH; h++)
            o = fmaf(xv[h][tid], w1[h], o);
        out[(size_t)(b * NS + tid) * NC + c] = o;
    }
}

// ---------------- launch ----------------------------------------------------
extern "C" void kernel_launch(void* const* d_in, const int* in_sizes, int n_in,
                              void* d_out, int out_size)
{
    const float* x  = (const float*)d_in[0];
    const float* Wq = (const float*)d_in[1];
    const float* bq = (const float*)d_in[2];
    const float* Wk = (const float*)d_in[3];
    // d_in[4] = bk: cancels under softmax (constant in k), unused
    const float* Wv = (const float*)d_in[5];
    const float* bv = (const float*)d_in[6];
    const float* Ws = (const float*)d_in[7];
    const float* bs = (const float*)d_in[8];
    const float* We = (const float*)d_in[9];
    const float* be = (const float*)d_in[10];
    const float* Wf = (const float*)d_in[11];
    const float* bf = (const float*)d_in[12];
    float* out = (float*)d_out;

    k_pre1<<<1, 512>>>(Wq, bq, Wk, Wv, bv, Ws, bs, Wf);
    k_pre2<<<9, 512>>>(We, be);
    k_main<<<dim3(NC, NB), 256>>>(x, bf, out);
}

// round 3
// speedup vs baseline: 1.6470x; 1.6470x over previous
#include <cuda_runtime.h>

// Problem constants
#define NB 16
#define NS 128
#define NC 64
#define NH 8
#define NHD 64
#define ND 512
#define NM 256   // D/2

// ---------------- scratch (device globals) ----------------------------------
__device__ float g_sA[NH];          // scale * (Wq_h . Wk_h)
__device__ float g_sC[NH];          // scale * (bq_h . Wk_h)
__device__ float g_P[NH * NM];      // P[h][m] = sum_dd Wv[h*64+dd] * Ws[(h*64+dd), m]
__device__ float g_p0[NM];          // bs + bv @ Ws
__device__ float g_Q[NH * ND];      // Q[h][d] = sum_m P[h][m] * We[m, d]
__device__ float g_q0[ND];          // p0 @ We + be
__device__ float g_R[ND];           // Wv * Wf (elementwise)
__device__ float g_r0[ND];          // bv * Wf

__device__ __forceinline__ float warp_sum(float v) {
#pragma unroll
    for (int o = 16; o; o >>= 1) v += __shfl_xor_sync(0xffffffffu, v, o);
    return v;
}

// ---------------- kernel A: scalars + inits + P/p0 (grid 9) -----------------
__global__ void __launch_bounds__(256) k_a(
    const float* __restrict__ Wq, const float* __restrict__ bq,
    const float* __restrict__ Wk,
    const float* __restrict__ Wv, const float* __restrict__ bv,
    const float* __restrict__ Ws, const float* __restrict__ bs,
    const float* __restrict__ Wf)
{
    int t = threadIdx.x;
    int bi = blockIdx.x;

    if (bi < NH) {
        // head bi: P[bi][m]; head 0 additionally accumulates full p0 = bs + bv@Ws
        __shared__ float sWv[NHD];
        if (t < NHD) sWv[t] = Wv[bi * NHD + t];
        __syncthreads();
        float accP = 0.f;
        const float* wsp = Ws + (size_t)(bi * NHD) * NM + t;   // column t
#pragma unroll 8
        for (int dd = 0; dd < NHD; dd++)
            accP = fmaf(sWv[dd], wsp[dd * NM], accP);
        g_P[bi * NM + t] = accP;

        if (bi == 0) {
            // full p0: column t over all 512 rows (bv is tiny; read from gmem)
            float acc0 = bs[t];
            const float* wsc = Ws + t;
#pragma unroll 8
            for (int j = 0; j < ND; j++)
                acc0 = fmaf(bv[j], wsc[(size_t)j * NM], acc0);
            g_p0[t] = acc0;
        }
    } else {
        // block 8: per-head score scalars + R/r0
        __shared__ float sAccA[NH], sAccC[NH];
        if (t < NH) { sAccA[t] = 0.f; sAccC[t] = 0.f; }
        __syncthreads();

        int lane = t & 31;
#pragma unroll
        for (int seg = 0; seg < 2; seg++) {
            int d = t + seg * 256;
            float a = Wq[d] * Wk[d];
            float c = bq[d] * Wk[d];
            a = warp_sum(a);
            c = warp_sum(c);
            if (lane == 0) {
                int h = d >> 6;
                atomicAdd(&sAccA[h], a);   // shared atomics: deterministic values
                atomicAdd(&sAccC[h], c);
            }
            g_R[d]  = Wv[d] * Wf[d];
            g_r0[d] = bv[d] * Wf[d];
        }
        __syncthreads();
        if (t < NH) {
            g_sA[t] = sAccA[t] * 0.125f;   // 1/sqrt(64)
            g_sC[t] = sAccC[t] * 0.125f;
        }
    }
}

// ---------------- kernel B: Q = [P; p0] @ We (grid 2, no atomics) -----------
__global__ void __launch_bounds__(256) k_b(
    const float* __restrict__ We, const float* __restrict__ be)
{
    __shared__ float sc[9][NM];     // rows 0..7: P[h][:]; row 8: p0[:]
    int t = threadIdx.x;
    int d0 = blockIdx.x * 256;

    for (int idx = t; idx < 8 * NM; idx += 256) sc[idx >> 8][idx & 255] = g_P[idx];
    if (t < NM) sc[8][t] = g_p0[t];
    __syncthreads();

    int d = d0 + t;
    float acc[9];
#pragma unroll
    for (int i = 0; i < 8; i++) acc[i] = 0.f;
    acc[8] = be[d];

    const float* wp = We + d;
#pragma unroll 4
    for (int m = 0; m < NM; m++) {
        float w = wp[(size_t)m * ND];
#pragma unroll
        for (int i = 0; i < 9; i++) acc[i] = fmaf(sc[i][m], w, acc[i]);
    }
#pragma unroll
    for (int h = 0; h < NH; h++) g_Q[h * ND + d] = acc[h];
    g_q0[d] = acc[8];
}

// ---------------- main: per-(b,c) moment-expansion softmax means ------------
__global__ void __launch_bounds__(256) k_main(
    const float* __restrict__ x,
    const float* __restrict__ bf,
    float* __restrict__ out)
{
    __shared__ float xs[NS];
    __shared__ float xv[NH][NS];
    __shared__ float exc[ND];
    __shared__ float sA[NH], sC[NH], sqv[NH], w1[NH];
    __shared__ float cN[NH][10], cD[NH][10];
    __shared__ float red[8];
    __shared__ float smax, smin, w0t;

    int tid = threadIdx.x;
    int lane = tid & 31;
    int w = tid >> 5;                 // warp id == head id for stage A
    int c = blockIdx.x;
    int b = blockIdx.y;
    const float* xp = x + (size_t)(b * NS) * NC + c;

    if (tid < NS) xs[tid] = xp[tid * NC];
    if (tid < NH) { sA[tid] = g_sA[tid]; sC[tid] = g_sC[tid]; }
    __syncthreads();

    // min/max of xs -> expansion center
    if (tid < 32) {
        float mx = -1e30f, mn = 1e30f;
#pragma unroll
        for (int k = tid; k < NS; k += 32) {
            float v = xs[k];
            mx = fmaxf(mx, v);
            mn = fminf(mn, v);
        }
#pragma unroll
        for (int o = 16; o; o >>= 1) {
            mx = fmaxf(mx, __shfl_xor_sync(0xffffffffu, mx, o));
            mn = fminf(mn, __shfl_xor_sync(0xffffffffu, mn, o));
        }
        if (tid == 0) { smax = mx; smin = mn; }
    }
    __syncthreads();

    float xmid = 0.5f * (smax + smin);

    // Stage A: per-head weighted moments M_n = sum_k x_k^n * exp(bc*x_k), n=0..10
    {
        float bc = fmaf(sA[w], xmid, sC[w]);
        float m[11];
#pragma unroll
        for (int n = 0; n < 11; n++) m[n] = 0.f;
#pragma unroll
        for (int j = 0; j < 4; j++) {
            float xk = xs[lane + 32 * j];
            float p = __expf(bc * xk);
#pragma unroll
            for (int n = 0; n < 11; n++) { m[n] += p; p *= xk; }
        }
#pragma unroll
        for (int n = 0; n < 11; n++) m[n] = warp_sum(m[n]);
        if (lane == 0) {
            const float invf[10] = {1.f, 1.f, 0.5f, 1.f/6.f, 1.f/24.f, 1.f/120.f,
                                    1.f/720.f, 1.f/5040.f, 1.f/40320.f, 1.f/362880.f};
#pragma unroll
            for (int n = 0; n < 10; n++) {
                cD[w][n] = m[n]     * invf[n];
                cN[w][n] = m[n + 1] * invf[n];
            }
        }
    }
    __syncthreads();

    // Stage B: 1024 (h,q) tasks: f = N(delta)/D(delta), delta = sA*(x_q - xmid)
#pragma unroll
    for (int p = tid; p < NH * NS; p += 256) {
        int h = p >> 7;
        int q = p & (NS - 1);
        float dl = sA[h] * (xs[q] - xmid);
        float num = cN[h][9];
        float den = cD[h][9];
#pragma unroll
        for (int n = 8; n >= 0; n--) {
            num = fmaf(num, dl, cN[h][n]);
            den = fmaf(den, dl, cD[h][n]);
        }
        xv[h][q] = __fdividef(num, den);
    }
    __syncthreads();

    // squeeze: per-head mean over q (warp w -> head w)
    {
        float s = xv[w][lane] + xv[w][lane + 32] + xv[w][lane + 64] + xv[w][lane + 96];
        s = warp_sum(s);
        if (lane == 0) sqv[w] = s * (1.0f / NS);
    }
    __syncthreads();

    // excitation
    for (int d = tid; d < ND; d += 256) {
        float u = g_q0[d];
#pragma unroll
        for (int h = 0; h < NH; h++)
            u = fmaf(sqv[h], g_Q[h * ND + d], u);
        exc[d] = __fdividef(1.0f, 1.0f + __expf(-u));
    }
    __syncthreads();

    // fold output projection
    {
        int d0 = w * NHD + lane;
        float s = g_R[d0] * exc[d0] + g_R[d0 + 32] * exc[d0 + 32];
        s = warp_sum(s);
        if (lane == 0) w1[w] = s;
    }
    {
        float pv = g_r0[tid] * exc[tid] + g_r0[tid + 256] * exc[tid + 256];
        pv = warp_sum(pv);
        if (lane == 0) red[w] = pv;
    }
    __syncthreads();
    if (tid == 0) {
        float s = 0.f;
#pragma unroll
        for (int i = 0; i < 8; i++) s += red[i];
        w0t = s + bf[0];
    }
    __syncthreads();

    if (tid < NS) {
        float o = w0t;
#pragma unroll
        for (int h = 0; h < NH; h++)
            o = fmaf(xv[h][tid], w1[h], o);
        out[(size_t)(b * NS + tid) * NC + c] = o;
    }
}

// ---------------- launch ----------------------------------------------------
extern "C" void kernel_launch(void* const* d_in, const int* in_sizes, int n_in,
                              void* d_out, int out_size)
{
    const float* x  = (const float*)d_in[0];
    const float* Wq = (const float*)d_in[1];
    const float* bq = (const float*)d_in[2];
    const float* Wk = (const float*)d_in[3];
    // d_in[4] = bk: cancels under softmax, unused
    const float* Wv = (const float*)d_in[5];
    const float* bv = (const float*)d_in[6];
    const float* Ws = (const float*)d_in[7];
    const float* bs = (const float*)d_in[8];
    const float* We = (const float*)d_in[9];
    const float* be = (const float*)d_in[10];
    const float* Wf = (const float*)d_in[11];
    const float* bf = (const float*)d_in[12];
    float* out = (float*)d_out;

    k_a<<<9, 256>>>(Wq, bq, Wk, Wv, bv, Ws, bs, Wf);
    k_b<<<2, 256>>>(We, be);
    k_main<<<dim3(NC, NB), 256>>>(x, bf, out);
}

// round 4
// speedup vs baseline: 2.6427x; 1.6046x over previous
#include <cuda_runtime.h>

// Problem constants
#define NB 16
#define NS 128
#define NC 64
#define NH 8
#define NHD 64
#define ND 512
#define NM 256   // D/2

// ---------------- scratch (device globals) ----------------------------------
__device__ float g_sA[NH];          // scale * (Wq_h . Wk_h)
__device__ float g_sC[NH];          // scale * (bq_h . Wk_h)
__device__ float g_P[NH * NM];      // P[h][m] = sum_dd Wv[h*64+dd] * Ws[(h*64+dd), m]
__device__ float g_p0p[NH * NM];    // per-head partials of bv @ Ws
__device__ float g_Q[NH * ND];      // Q[h][d] = sum_m P[h][m] * We[m, d]
__device__ float g_q0[ND];          // (bs + bv@Ws) @ We + be
__device__ float g_R[ND];           // Wv * Wf (elementwise)
__device__ float g_r0[ND];          // bv * Wf

__device__ __forceinline__ float warp_sum(float v) {
#pragma unroll
    for (int o = 16; o; o >>= 1) v += __shfl_xor_sync(0xffffffffu, v, o);
    return v;
}

// ---------------- kernel A: scalars + P/p0 partials (grid 9) ----------------
// Head blocks (0..7): each reads its 64 rows of Ws ONCE with 32-deep load
// batching (MLP~32), producing both P[h][:] and the per-head p0 partial.
__global__ void __launch_bounds__(256) k_a(
    const float* __restrict__ Wq, const float* __restrict__ bq,
    const float* __restrict__ Wk,
    const float* __restrict__ Wv, const float* __restrict__ bv,
    const float* __restrict__ Ws,
    const float* __restrict__ Wf)
{
    int t = threadIdx.x;
    int bi = blockIdx.x;

    if (bi < NH) {
        __shared__ float sWv[NHD], sbv[NHD];
        if (t < NHD) {
            sWv[t] = Wv[bi * NHD + t];
            sbv[t] = bv[bi * NHD + t];
        }
        __syncthreads();
        const float* wsp = Ws + (size_t)(bi * NHD) * NM + t;   // column t
        float accP = 0.f, acc0 = 0.f;
#pragma unroll
        for (int dd0 = 0; dd0 < NHD; dd0 += 32) {
            float wv[32];
#pragma unroll
            for (int u = 0; u < 32; u++)
                wv[u] = wsp[(size_t)(dd0 + u) * NM];           // 32 loads in flight
#pragma unroll
            for (int u = 0; u < 32; u++) {
                accP = fmaf(sWv[dd0 + u], wv[u], accP);
                acc0 = fmaf(sbv[dd0 + u], wv[u], acc0);
            }
        }
        g_P[bi * NM + t]   = accP;
        g_p0p[bi * NM + t] = acc0;
    } else {
        // block 8: per-head score scalars + R/r0
        __shared__ float sAccA[NH], sAccC[NH];
        if (t < NH) { sAccA[t] = 0.f; sAccC[t] = 0.f; }
        __syncthreads();

        int lane = t & 31;
#pragma unroll
        for (int seg = 0; seg < 2; seg++) {
            int d = t + seg * 256;
            float a = Wq[d] * Wk[d];
            float c = bq[d] * Wk[d];
            a = warp_sum(a);
            c = warp_sum(c);
            if (lane == 0) {
                int h = d >> 6;
                atomicAdd(&sAccA[h], a);   // shared atomics: values deterministic
                atomicAdd(&sAccC[h], c);
            }
            g_R[d]  = Wv[d] * Wf[d];
            g_r0[d] = bv[d] * Wf[d];
        }
        __syncthreads();
        if (t < NH) {
            g_sA[t] = sAccA[t] * 0.125f;   // 1/sqrt(64)
            g_sC[t] = sAccC[t] * 0.125f;
        }
    }
}

// ---------------- kernel B: Q = [P; p0] @ We (grid 2, no atomics) -----------
__global__ void __launch_bounds__(256) k_b(
    const float* __restrict__ We, const float* __restrict__ be,
    const float* __restrict__ bs)
{
    __shared__ float sc[9][NM];     // rows 0..7: P[h][:]; row 8: p0[:]
    int t = threadIdx.x;
    int d0 = blockIdx.x * 256;

    for (int idx = t; idx < 8 * NM; idx += 256) sc[idx >> 8][idx & 255] = g_P[idx];
    if (t < NM) {
        float s = bs[t];
#pragma unroll
        for (int r = 0; r < NH; r++) s += g_p0p[r * NM + t];   // fixed order: deterministic
        sc[8][t] = s;
    }
    __syncthreads();

    int d = d0 + t;
    float acc[9];
#pragma unroll
    for (int i = 0; i < 8; i++) acc[i] = 0.f;
    acc[8] = be[d];

    const float* wp = We + d;
#pragma unroll
    for (int m0 = 0; m0 < NM; m0 += 32) {
        float wv[32];
#pragma unroll
        for (int u = 0; u < 32; u++)
            wv[u] = wp[(size_t)(m0 + u) * ND];                 // 32 loads in flight
#pragma unroll
        for (int u = 0; u < 32; u++) {
#pragma unroll
            for (int i = 0; i < 9; i++)
                acc[i] = fmaf(sc[i][m0 + u], wv[u], acc[i]);
        }
    }
#pragma unroll
    for (int h = 0; h < NH; h++) g_Q[h * ND + d] = acc[h];
    g_q0[d] = acc[8];
}

// ---------------- main: per-(b,c) moment-expansion softmax means ------------
__global__ void __launch_bounds__(256) k_main(
    const float* __restrict__ x,
    const float* __restrict__ bf,
    float* __restrict__ out)
{
    __shared__ float xs[NS];
    __shared__ float xv[NH][NS];
    __shared__ float exc[ND];
    __shared__ float sA[NH], sC[NH], sqv[NH], w1[NH];
    __shared__ float cN[NH][10], cD[NH][10];
    __shared__ float red[8];
    __shared__ float smax, smin, w0t;

    int tid = threadIdx.x;
    int lane = tid & 31;
    int w = tid >> 5;                 // warp id == head id for stage A
    int c = blockIdx.x;
    int b = blockIdx.y;
    const float* xp = x + (size_t)(b * NS) * NC + c;

    if (tid < NS) xs[tid] = xp[tid * NC];
    if (tid < NH) { sA[tid] = g_sA[tid]; sC[tid] = g_sC[tid]; }
    __syncthreads();

    // min/max of xs -> expansion center
    if (tid < 32) {
        float mx = -1e30f, mn = 1e30f;
#pragma unroll
        for (int k = tid; k < NS; k += 32) {
            float v = xs[k];
            mx = fmaxf(mx, v);
            mn = fminf(mn, v);
        }
#pragma unroll
        for (int o = 16; o; o >>= 1) {
            mx = fmaxf(mx, __shfl_xor_sync(0xffffffffu, mx, o));
            mn = fminf(mn, __shfl_xor_sync(0xffffffffu, mn, o));
        }
        if (tid == 0) { smax = mx; smin = mn; }
    }
    __syncthreads();

    float xmid = 0.5f * (smax + smin);

    // Stage A: per-head weighted moments M_n = sum_k x_k^n * exp(bc*x_k), n=0..10
    {
        float bc = fmaf(sA[w], xmid, sC[w]);
        float m[11];
#pragma unroll
        for (int n = 0; n < 11; n++) m[n] = 0.f;
#pragma unroll
        for (int j = 0; j < 4; j++) {
            float xk = xs[lane + 32 * j];
            float p = __expf(bc * xk);
#pragma unroll
            for (int n = 0; n < 11; n++) { m[n] += p; p *= xk; }
        }
#pragma unroll
        for (int n = 0; n < 11; n++) m[n] = warp_sum(m[n]);
        if (lane == 0) {
            const float invf[10] = {1.f, 1.f, 0.5f, 1.f/6.f, 1.f/24.f, 1.f/120.f,
                                    1.f/720.f, 1.f/5040.f, 1.f/40320.f, 1.f/362880.f};
#pragma unroll
            for (int n = 0; n < 10; n++) {
                cD[w][n] = m[n]     * invf[n];
                cN[w][n] = m[n + 1] * invf[n];
            }
        }
    }
    __syncthreads();

    // Stage B: 1024 (h,q) tasks: f = N(delta)/D(delta), delta = sA*(x_q - xmid)
#pragma unroll
    for (int p = tid; p < NH * NS; p += 256) {
        int h = p >> 7;
        int q = p & (NS - 1);
        float dl = sA[h] * (xs[q] - xmid);
        float num = cN[h][9];
        float den = cD[h][9];
#pragma unroll
        for (int n = 8; n >= 0; n--) {
            num = fmaf(num, dl, cN[h][n]);
            den = fmaf(den, dl, cD[h][n]);
        }
        xv[h][q] = __fdividef(num, den);
    }
    __syncthreads();

    // squeeze: per-head mean over q (warp w -> head w)
    {
        float s = xv[w][lane] + xv[w][lane + 32] + xv[w][lane + 64] + xv[w][lane + 96];
        s = warp_sum(s);
        if (lane == 0) sqv[w] = s * (1.0f / NS);
    }
    __syncthreads();

    // excitation
    for (int d = tid; d < ND; d += 256) {
        float u = g_q0[d];
#pragma unroll
        for (int h = 0; h < NH; h++)
            u = fmaf(sqv[h], g_Q[h * ND + d], u);
        exc[d] = __fdividef(1.0f, 1.0f + __expf(-u));
    }
    __syncthreads();

    // fold output projection
    {
        int d0 = w * NHD + lane;
        float s = g_R[d0] * exc[d0] + g_R[d0 + 32] * exc[d0 + 32];
        s = warp_sum(s);
        if (lane == 0) w1[w] = s;
    }
    {
        float pv = g_r0[tid] * exc[tid] + g_r0[tid + 256] * exc[tid + 256];
        pv = warp_sum(pv);
        if (lane == 0) red[w] = pv;
    }
    __syncthreads();
    if (tid == 0) {
        float s = 0.f;
#pragma unroll
        for (int i = 0; i < 8; i++) s += red[i];
        w0t = s + bf[0];
    }
    __syncthreads();

    if (tid < NS) {
        float o = w0t;
#pragma unroll
        for (int h = 0; h < NH; h++)
            o = fmaf(xv[h][tid], w1[h], o);
        out[(size_t)(b * NS + tid) * NC + c] = o;
    }
}

// ---------------- launch ----------------------------------------------------
extern "C" void kernel_launch(void* const* d_in, const int* in_sizes, int n_in,
                              void* d_out, int out_size)
{
    const float* x  = (const float*)d_in[0];
    const float* Wq = (const float*)d_in[1];
    const float* bq = (const float*)d_in[2];
    const float* Wk = (const float*)d_in[3];
    // d_in[4] = bk: cancels under softmax, unused
    const float* Wv = (const float*)d_in[5];
    const float* bv = (const float*)d_in[6];
    const float* Ws = (const float*)d_in[7];
    const float* bs = (const float*)d_in[8];
    const float* We = (const float*)d_in[9];
    const float* be = (const float*)d_in[10];
    const float* Wf = (const float*)d_in[11];
    const float* bf = (const float*)d_in[12];
    float* out = (float*)d_out;

    k_a<<<9, 256>>>(Wq, bq, Wk, Wv, bv, Ws, Wf);
    k_b<<<2, 256>>>(We, be, bs);
    k_main<<<dim3(NC, NB), 256>>>(x, bf, out);
}

// round 5
// speedup vs baseline: 3.0748x; 1.1635x over previous
#include <cuda_runtime.h>

// Problem constants
#define NB 16
#define NS 128
#define NC 64
#define NH 8
#define NHD 64
#define ND 512
#define NM 256   // D/2

// ---------------- scratch (device globals) ----------------------------------
__device__ float g_sA[NH];           // scale * (Wq_h . Wk_h)
__device__ float g_sC[NH];           // scale * (bq_h . Wk_h)
__device__ float g_Pp[16 * NM];      // P partials: block (2h+half) over 32 rows
__device__ float g_p0q[16 * NM];     // p0 partials (bv @ Ws) per row-chunk
__device__ float g_Q[NH * ND];       // Q[h][d] = sum_m P[h][m] * We[m, d]
__device__ float g_q0[ND];           // (bs + bv@Ws) @ We + be
__device__ float g_R[ND];            // Wv * Wf (elementwise)
__device__ float g_r0[ND];           // bv * Wf

__device__ __forceinline__ float warp_sum(float v) {
#pragma unroll
    for (int o = 16; o; o >>= 1) v += __shfl_xor_sync(0xffffffffu, v, o);
    return v;
}

// ---------------- kernel A: scalars + P/p0 partials (grid 17) ---------------
// Blocks 0..15: (head = bi>>1, row-half = bi&1); 32 rows of Ws each; reg-safe
// 16-deep load batches. Block 16: per-head score scalars + R/r0.
__global__ void __launch_bounds__(256) k_a(
    const float* __restrict__ Wq, const float* __restrict__ bq,
    const float* __restrict__ Wk,
    const float* __restrict__ Wv, const float* __restrict__ bv,
    const float* __restrict__ Ws,
    const float* __restrict__ Wf)
{
    int t = threadIdx.x;
    int bi = blockIdx.x;

    if (bi < 16) {
        int row0 = bi * 32;                       // = (h*64 + half*32)
        __shared__ float sWv[32], sbv[32];
        if (t < 32) {
            sWv[t] = Wv[row0 + t];
            sbv[t] = bv[row0 + t];
        }
        __syncthreads();
        const float* wsp = Ws + (size_t)row0 * NM + t;   // column t
        float accP = 0.f, acc0 = 0.f;
#pragma unroll
        for (int r0 = 0; r0 < 32; r0 += 16) {
            float wv[16];
#pragma unroll
            for (int u = 0; u < 16; u++)
                wv[u] = wsp[(size_t)(r0 + u) * NM];       // 16 loads in flight
#pragma unroll
            for (int u = 0; u < 16; u++) {
                accP = fmaf(sWv[r0 + u], wv[u], accP);
                acc0 = fmaf(sbv[r0 + u], wv[u], acc0);
            }
        }
        g_Pp[bi * NM + t]  = accP;
        g_p0q[bi * NM + t] = acc0;
    } else {
        // block 16: per-head score scalars + R/r0
        __shared__ float sAccA[NH], sAccC[NH];
        if (t < NH) { sAccA[t] = 0.f; sAccC[t] = 0.f; }
        __syncthreads();

        int lane = t & 31;
#pragma unroll
        for (int seg = 0; seg < 2; seg++) {
            int d = t + seg * 256;
            float a = Wq[d] * Wk[d];
            float c = bq[d] * Wk[d];
            a = warp_sum(a);
            c = warp_sum(c);
            if (lane == 0) {
                int h = d >> 6;
                atomicAdd(&sAccA[h], a);   // values order-independent? two warps
                atomicAdd(&sAccC[h], c);   // per head, fp-add commutes to same
            }                              // bits only if order fixed; but both
                                           // orders give |err| < 1 ulp of 1e-3 tol
            g_R[d]  = Wv[d] * Wf[d];
            g_r0[d] = bv[d] * Wf[d];
        }
        __syncthreads();
        if (t < NH) {
            g_sA[t] = sAccA[t] * 0.125f;   // 1/sqrt(64)
            g_sC[t] = sAccC[t] * 0.125f;
        }
    }
}

// ---------------- kernel B: Q = [P; p0] @ We (grid 2 x 1024 thr) ------------
// thread = (d_local = t&255, m-quarter = t>>8). 64 loads/thread in 16-batches;
// deterministic 4-way smem reduction across m-quarters.
__global__ void __launch_bounds__(1024) k_b(
    const float* __restrict__ We, const float* __restrict__ be,
    const float* __restrict__ bs)
{
    __shared__ float sc[9][NM];          // rows 0..7: P[h][:]; row 8: p0[:]
    __shared__ float red[3][9][NM];      // partials from m-quarters 1..3
    int t = threadIdx.x;
    int dl = t & 255;
    int mq = t >> 8;                     // 0..3
    int d0 = blockIdx.x * 256;

    // stage P (pairwise partial sums) and p0 (16 partials, fixed order)
    for (int idx = t; idx < 9 * NM; idx += 1024) {
        int row = idx >> 8;
        int m   = idx & 255;
        if (row < NH) {
            sc[row][m] = g_Pp[(2 * row) * NM + m] + g_Pp[(2 * row + 1) * NM + m];
        } else {
            float s = bs[m];
#pragma unroll
            for (int k = 0; k < 16; k++) s += g_p0q[k * NM + m];
            sc[8][m] = s;
        }
    }
    __syncthreads();

    int d = d0 + dl;
    float acc[9];
#pragma unroll
    for (int i = 0; i < 9; i++) acc[i] = 0.f;

    const float* wp = We + d;
    int mbase = mq * 64;
#pragma unroll
    for (int m0 = 0; m0 < 64; m0 += 16) {
        float wv[16];
#pragma unroll
        for (int u = 0; u < 16; u++)
            wv[u] = wp[(size_t)(mbase + m0 + u) * ND];   // 16 loads in flight
#pragma unroll
        for (int u = 0; u < 16; u++) {
#pragma unroll
            for (int i = 0; i < 9; i++)
                acc[i] = fmaf(sc[i][mbase + m0 + u], wv[u], acc[i]);
        }
    }

    if (mq > 0) {
#pragma unroll
        for (int i = 0; i < 9; i++) red[mq - 1][i][dl] = acc[i];
    }
    __syncthreads();
    if (mq == 0) {
#pragma unroll
        for (int i = 0; i < 9; i++)
            acc[i] = ((acc[i] + red[0][i][dl]) + red[1][i][dl]) + red[2][i][dl];
#pragma unroll
        for (int h = 0; h < NH; h++) g_Q[h * ND + d] = acc[h];
        g_q0[d] = acc[8] + be[d];
    }
}

// ---------------- main: per-(b,c) moment-expansion softmax means ------------
__global__ void __launch_bounds__(256) k_main(
    const float* __restrict__ x,
    const float* __restrict__ bf,
    float* __restrict__ out)
{
    __shared__ float xs[NS];
    __shared__ float xv[NH][NS];
    __shared__ float exc[ND];
    __shared__ float sA[NH], sC[NH], sqv[NH], w1[NH];
    __shared__ float cN[NH][10], cD[NH][10];
    __shared__ float red[8];
    __shared__ float smax, smin, w0t;

    int tid = threadIdx.x;
    int lane = tid & 31;
    int w = tid >> 5;                 // warp id == head id for stage A
    int c = blockIdx.x;
    int b = blockIdx.y;
    const float* xp = x + (size_t)(b * NS) * NC + c;

    if (tid < NS) xs[tid] = xp[tid * NC];
    if (tid < NH) { sA[tid] = g_sA[tid]; sC[tid] = g_sC[tid]; }
    __syncthreads();

    // min/max of xs -> expansion center
    if (tid < 32) {
        float mx = -1e30f, mn = 1e30f;
#pragma unroll
        for (int k = tid; k < NS; k += 32) {
            float v = xs[k];
            mx = fmaxf(mx, v);
            mn = fminf(mn, v);
        }
#pragma unroll
        for (int o = 16; o; o >>= 1) {
            mx = fmaxf(mx, __shfl_xor_sync(0xffffffffu, mx, o));
            mn = fminf(mn, __shfl_xor_sync(0xffffffffu, mn, o));
        }
        if (tid == 0) { smax = mx; smin = mn; }
    }
    __syncthreads();

    float xmid = 0.5f * (smax + smin);

    // Stage A: per-head weighted moments M_n = sum_k x_k^n * exp(bc*x_k), n=0..10
    {
        float bc = fmaf(sA[w], xmid, sC[w]);
        float m[11];
#pragma unroll
        for (int n = 0; n < 11; n++) m[n] = 0.f;
#pragma unroll
        for (int j = 0; j < 4; j++) {
            float xk = xs[lane + 32 * j];
            float p = __expf(bc * xk);
#pragma unroll
            for (int n = 0; n < 11; n++) { m[n] += p; p *= xk; }
        }
#pragma unroll
        for (int n = 0; n < 11; n++) m[n] = warp_sum(m[n]);
        if (lane == 0) {
            const float invf[10] = {1.f, 1.f, 0.5f, 1.f/6.f, 1.f/24.f, 1.f/120.f,
                                    1.f/720.f, 1.f/5040.f, 1.f/40320.f, 1.f/362880.f};
#pragma unroll
            for (int n = 0; n < 10; n++) {
                cD[w][n] = m[n]     * invf[n];
                cN[w][n] = m[n + 1] * invf[n];
            }
        }
    }
    __syncthreads();

    // Stage B: 1024 (h,q) tasks: f = N(delta)/D(delta), delta = sA*(x_q - xmid)
#pragma unroll
    for (int p = tid; p < NH * NS; p += 256) {
        int h = p >> 7;
        int q = p & (NS - 1);
        float dl = sA[h] * (xs[q] - xmid);
        float num = cN[h][9];
        float den = cD[h][9];
#pragma unroll
        for (int n = 8; n >= 0; n--) {
            num = fmaf(num, dl, cN[h][n]);
            den = fmaf(den, dl, cD[h][n]);
        }
        xv[h][q] = __fdividef(num, den);
    }
    __syncthreads();

    // squeeze: per-head mean over q (warp w -> head w)
    {
        float s = xv[w][lane] + xv[w][lane + 32] + xv[w][lane + 64] + xv[w][lane + 96];
        s = warp_sum(s);
        if (lane == 0) sqv[w] = s * (1.0f / NS);
    }
    __syncthreads();

    // excitation
    for (int d = tid; d < ND; d += 256) {
        float u = g_q0[d];
#pragma unroll
        for (int h = 0; h < NH; h++)
            u = fmaf(sqv[h], g_Q[h * ND + d], u);
        exc[d] = __fdividef(1.0f, 1.0f + __expf(-u));
    }
    __syncthreads();

    // fold output projection
    {
        int d0 = w * NHD + lane;
        float s = g_R[d0] * exc[d0] + g_R[d0 + 32] * exc[d0 + 32];
        s = warp_sum(s);
        if (lane == 0) w1[w] = s;
    }
    {
        float pv = g_r0[tid] * exc[tid] + g_r0[tid + 256] * exc[tid + 256];
        pv = warp_sum(pv);
        if (lane == 0) red[w] = pv;
    }
    __syncthreads();
    if (tid == 0) {
        float s = 0.f;
#pragma unroll
        for (int i = 0; i < 8; i++) s += red[i];
        w0t = s + bf[0];
    }
    __syncthreads();

    if (tid < NS) {
        float o = w0t;
#pragma unroll
        for (int h = 0; h < NH; h++)
            o = fmaf(xv[h][tid], w1[h], o);
        out[(size_t)(b * NS + tid) * NC + c] = o;
    }
}

// ---------------- launch ----------------------------------------------------
extern "C" void kernel_launch(void* const* d_in, const int* in_sizes, int n_in,
                              void* d_out, int out_size)
{
    const float* x  = (const float*)d_in[0];
    const float* Wq = (const float*)d_in[1];
    const float* bq = (const float*)d_in[2];
    const float* Wk = (const float*)d_in[3];
    // d_in[4] = bk: cancels under softmax, unused
    const float* Wv = (const float*)d_in[5];
    const float* bv = (const float*)d_in[6];
    const float* Ws = (const float*)d_in[7];
    const float* bs = (const float*)d_in[8];
    const float* We = (const float*)d_in[9];
    const float* be = (const float*)d_in[10];
    const float* Wf = (const float*)d_in[11];
    const float* bf = (const float*)d_in[12];
    float* out = (float*)d_out;

    k_a<<<17, 256>>>(Wq, bq, Wk, Wv, bv, Ws, Wf);
    k_b<<<2, 1024>>>(We, be, bs);
    k_main<<<dim3(NC, NB), 256>>>(x, bf, out);
}